// round 14
// baseline (speedup 1.0000x reference)
#include <cuda_runtime.h>
#include <cuda_bf16.h>

#define BB 128
#define UU 8
#define CC 2048
#define JJ 32
#define SS 16
#define NITER 3

#define JS   (JJ*SS)     // 512
#define SU   (SS*UU)     // 128
#define JSU  (JJ*SS*UU)  // 4096
#define UC   (UU*CC)     // 16384
#define CB   (CC*BB)     // 262144
#define NCHUNK 64        // 64 chunks of 32 c

typedef unsigned long long ull;

// ---------------- packed f32x2 helpers ---------------------------------------
__device__ __forceinline__ ull pk2(float lo, float hi) {
    ull r; asm("mov.b64 %0, {%1, %2};" : "=l"(r) : "f"(lo), "f"(hi)); return r;
}
__device__ __forceinline__ void fma2(ull& d, ull a, ull b) {
    asm("fma.rn.f32x2 %0, %1, %2, %0;" : "+l"(d) : "l"(a), "l"(b));
}
__device__ __forceinline__ void add2(ull& d, ull a) {
    asm("add.rn.f32x2 %0, %0, %1;" : "+l"(d) : "l"(a));
}
__device__ __forceinline__ void upk2(float& lo, float& hi, ull v) {
    asm("mov.b64 {%0, %1}, %2;" : "=f"(lo), "=f"(hi) : "l"(v));
}

// bf16 mma m16n8k16: D = A(row-major) * B(col-major) + C, f32 accum
__device__ __forceinline__ void mma_bf16(float* c, unsigned a0, unsigned a1,
                                         unsigned a2, unsigned a3,
                                         unsigned b0, unsigned b1) {
    asm volatile(
        "mma.sync.aligned.m16n8k16.row.col.f32.bf16.bf16.f32 "
        "{%0,%1,%2,%3}, {%4,%5,%6,%7}, {%8,%9}, {%0,%1,%2,%3};"
        : "+f"(c[0]), "+f"(c[1]), "+f"(c[2]), "+f"(c[3])
        : "r"(a0), "r"(a1), "r"(a2), "r"(a3), "r"(b0), "r"(b1));
}

// ---------------- device scratch ----------------------------------------------
__device__ float g_xT[UU*CC*BB + 256];   // [u][c][b]  8 MB
__device__ float g_Wr[CC*JSU];           // [c][j][u][s] 33.5 MB
__device__ float g_b[JJ*CC];             // logits [j][c]
__device__ float g_c[JJ*CC];             // coeffs [j][c]
__device__ float g_sp[NCHUNK*BB*JS];     // partial s, 16 MB
__device__ float g_bp[UU*JJ*CC];         // per-u partial b-updates [u][j][c], 2 MB
__device__ unsigned short g_xa[2][UC*BB]; // xT bf16 hi/lo planes [uc][b], 2x4 MB
__device__ unsigned short g_vb[2][JS*BB]; // v  bf16 hi/lo planes [js][b], 2x128 KB

// ---------------- fused setup: transpose x, reorder W, init b/c ----------------
__global__ void __launch_bounds__(256) setup_k(const float* __restrict__ x,
                                               const float* __restrict__ Wg) {
    int bid = blockIdx.x;
    int t   = threadIdx.x;
    if (bid < 2048) {
        __shared__ float tile[32][33];
        int ct = bid & 63;
        int bt = (bid >> 6) & 3;
        int u  = bid >> 8;
        int c0 = ct * 32, b0 = bt * 32;
        int tx = t & 31, ty8 = t >> 5;
        #pragma unroll
        for (int r = 0; r < 4; r++) {
            int ty = ty8 + r * 8;
            tile[ty][tx] = x[(size_t)(b0 + ty) * UC + u * CC + c0 + tx];
        }
        __syncthreads();
        #pragma unroll
        for (int r = 0; r < 4; r++) {
            int ty = ty8 + r * 8;
            g_xT[(size_t)u * CB + (size_t)(c0 + ty) * BB + b0 + tx] = tile[tx][ty];
        }
    } else if (bid < 2048 + 32768) {
        int row = (bid - 2048) * 2 + (t >> 7);
        int tt  = t & 127;
        int u = tt >> 4, s = tt & 15;
        g_Wr[(size_t)row * SU + tt] = Wg[(size_t)row * SU + s * UU + u];
    } else {
        int i = (bid - 2048 - 32768) * 256 + t;
        ((float4*)g_b)[i] = make_float4(0.f, 0.f, 0.f, 0.f);
        float cv = 1.0f / 2048.0f;
        ((float4*)g_c)[i] = make_float4(cv, cv, cv, cv);
    }
}

// ---------------- setup2: bf16 hi/lo planes of xT ------------------------------
__global__ void __launch_bounds__(256) setup2_k() {
    int base = blockIdx.x * 256 * 32;   // 256 blocks
    int t = threadIdx.x;
    #pragma unroll 8
    for (int i = 0; i < 32; i++) {
        int idx = base + i * 256 + t;
        float val = g_xT[idx];
        __nv_bfloat16 hb = __float2bfloat16(val);
        __nv_bfloat16 lb = __float2bfloat16(val - __bfloat162float(hb));
        g_xa[0][idx] = __bfloat16_as_ushort(hb);
        g_xa[1][idx] = __bfloat16_as_ushort(lb);
    }
}

// ---------------- fused s-pass (warp = 1 j, 8 c, all 128 b, 16 s) ----------------
__global__ void __launch_bounds__(256, 2) s_pass_k() {
    int j0    = blockIdx.x * 2;
    int chunk = blockIdx.y;
    int t     = threadIdx.x;
    int w = t >> 5, lane = t & 31;
    int jj = w & 1, cq = w >> 1;
    int cbase = chunk * 32;

    __shared__ __align__(16) float wsm[2 * 32 * 128];

    {
        const float4* Wr4 = (const float4*)g_Wr;
        float4* w4 = (float4*)wsm;
        #pragma unroll
        for (int i = 0; i < 8; i++) {
            int lin = i * 256 + t;
            int sj = lin >> 10;
            int rem = lin & 1023;
            int cl = rem >> 5, q = rem & 31;
            float coef = __ldg(&g_c[(j0 + sj) * CC + cbase + cl]);
            float4 wv = Wr4[(size_t)(cbase + cl) * (JSU/4) + (j0 + sj) * 32 + q];
            wv.x *= coef; wv.y *= coef; wv.z *= coef; wv.w *= coef;
            w4[sj * 1024 + cl * 32 + q] = wv;
        }
    }
    __syncthreads();

    ull acc[4][8];
    #pragma unroll
    for (int bi = 0; bi < 4; bi++)
        #pragma unroll
        for (int sp = 0; sp < 8; sp++) acc[bi][sp] = 0ULL;

    const float* xrow0 = g_xT + (size_t)(cbase + cq * 8) * BB + lane * 4;
    const float* wwarp = &wsm[jj * 4096 + cq * 8 * 128];

    float4 x0 = *(const float4*)(xrow0);
    float4 x1 = *(const float4*)(xrow0 + CB);

    #pragma unroll 1
    for (int k = 0; k < 8; k++) {
        const float* xrow = xrow0 + k * BB;
        #pragma unroll
        for (int u = 0; u < UU; u++) {
            float4 x2 = *(const float4*)(xrow + ((u + 2) & 7) * CB + ((u + 2) >> 3) * BB);

            ull xd0 = pk2(x0.x, x0.x), xd1 = pk2(x0.y, x0.y);
            ull xd2 = pk2(x0.z, x0.z), xd3 = pk2(x0.w, x0.w);
            const ulonglong2* w2 = (const ulonglong2*)(wwarp + k * 128 + u * 16);
            ulonglong2 wv0 = w2[0], wv1 = w2[1], wv2 = w2[2], wv3 = w2[3];
            ull wp[8] = {wv0.x, wv0.y, wv1.x, wv1.y, wv2.x, wv2.y, wv3.x, wv3.y};
            #pragma unroll
            for (int sp = 0; sp < 8; sp++) {
                fma2(acc[0][sp], wp[sp], xd0);
                fma2(acc[1][sp], wp[sp], xd1);
                fma2(acc[2][sp], wp[sp], xd2);
                fma2(acc[3][sp], wp[sp], xd3);
            }
            x0 = x1; x1 = x2;
        }
    }

    __syncthreads();
    ull* redU = (ull*)wsm;
    if (cq >= 2) {
        #pragma unroll
        for (int bi = 0; bi < 4; bi++)
            #pragma unroll
            for (int sp = 0; sp < 8; sp++)
                redU[jj*2048 + (cq-2)*1024 + sp*128 + bi*32 + lane] = acc[bi][sp];
    }
    __syncthreads();
    if (cq < 2) {
        #pragma unroll
        for (int bi = 0; bi < 4; bi++)
            #pragma unroll
            for (int sp = 0; sp < 8; sp++) {
                int idx = jj*2048 + cq*1024 + sp*128 + bi*32 + lane;
                ull s = redU[idx];
                add2(s, acc[bi][sp]);
                redU[idx] = s;
            }
    }
    __syncthreads();

    {
        int sj = t >> 7, slot = t & 127;
        int b = (slot & 31) * 4 + (slot >> 5);
        float res[16];
        #pragma unroll
        for (int sp = 0; sp < 8; sp++) {
            ull s = redU[sj*2048 + sp*128 + slot];
            add2(s, redU[sj*2048 + 1024 + sp*128 + slot]);
            upk2(res[2*sp], res[2*sp+1], s);
        }
        float4* dst = (float4*)&g_sp[(size_t)chunk * (BB*JS) + b * JS + (j0 + sj) * SS];
        #pragma unroll
        for (int q = 0; q < 4; q++)
            dst[q] = make_float4(res[q*4], res[q*4+1], res[q*4+2], res[q*4+3]);
    }
}

// ---------------- reduce partials + squash -> v (+ v bf16 planes) --------------
__global__ void squash_k(float* __restrict__ out, int make_vt) {
    int b = blockIdx.x;      // 128
    int t = threadIdx.x;     // 512 = js
    float sv = 0.0f;
    #pragma unroll 8
    for (int k = 0; k < NCHUNK; k++)
        sv += g_sp[(size_t)k * (BB*JS) + b * JS + t];

    __shared__ float sq[512];
    __shared__ float msqs[SS];
    sq[t] = sv * sv;
    __syncthreads();
    if (t < SS) {
        float m = 0.0f;
        #pragma unroll
        for (int jj = 0; jj < JJ; jj++) m += sq[jj * SS + t];
        msqs[t] = m;
    }
    __syncthreads();
    float msq = msqs[t & (SS - 1)];
    float scale = msq / ((1.0f + msq) * sqrtf(msq));
    float val = sv * scale;
    out[b * JS + t] = val;

    if (make_vt) {
        __nv_bfloat16 hb = __float2bfloat16(val);
        __nv_bfloat16 lb = __float2bfloat16(val - __bfloat162float(hb));
        g_vb[0][t * BB + b] = __bfloat16_as_ushort(hb);
        g_vb[1][t * BB + b] = __bfloat16_as_ushort(lb);
    }
}

// ---------------- HMMA M-GEMM + fused b-update epilogue -------------------------
// M[uc][js] = sum_b xT[uc][b] * v[b][js]  (A row-major [m][k], B col-major via
// g_vb [n][k]). bf16 hi/lo 3-term. CTA = m64 x n64, K=128 in one pass.
// smem: Bs 2 planes x 64 n x 68 words (b32, 2 bf16 each) = 34816 B; Ms aliased.
#define MM_SMEM 34816
__global__ void __launch_bounds__(128, 3) mgemm_mma_k() {
    extern __shared__ __align__(16) unsigned mms[];
    int t = threadIdx.x, w = t >> 5, lane = t & 31;
    int g = lane >> 2, tg = lane & 3;
    int nb = blockIdx.x;   // 8  -> n0 = nb*64
    int mb = blockIdx.y;   // 256 -> m0 = mb*64

    // stage B planes into smem: Bs[p][n][kw] pitch 68 words
    #pragma unroll
    for (int p = 0; p < 2; p++) {
        const unsigned* src = (const unsigned*)(&g_vb[p][(size_t)nb * 64 * BB]);
        unsigned* dst = mms + p * (64 * 68);
        #pragma unroll
        for (int i = 0; i < 32; i++) {
            int word = i * 128 + t;          // 0..4095
            int n = word >> 6, kw = word & 63;
            dst[n * 68 + kw] = src[word];
        }
    }
    __syncthreads();

    float acc[8][4];
    #pragma unroll
    for (int nt = 0; nt < 8; nt++)
        #pragma unroll
        for (int q = 0; q < 4; q++) acc[nt][q] = 0.0f;

    int m0 = mb * 64 + w * 16;
    const int pa_[3] = {0, 0, 1}, pb_[3] = {0, 1, 0};
    #pragma unroll
    for (int cb = 0; cb < 3; cb++) {
        const unsigned short* A = g_xa[pa_[cb]];
        const unsigned* Bsp = mms + pb_[cb] * (64 * 68);
        #pragma unroll
        for (int ks = 0; ks < 8; ks++) {
            int col = ks * 16 + tg * 2;
            unsigned a0 = *(const unsigned*)(A + (size_t)(m0 + g)     * BB + col);
            unsigned a1 = *(const unsigned*)(A + (size_t)(m0 + g + 8) * BB + col);
            unsigned a2 = *(const unsigned*)(A + (size_t)(m0 + g)     * BB + col + 8);
            unsigned a3 = *(const unsigned*)(A + (size_t)(m0 + g + 8) * BB + col + 8);
            #pragma unroll
            for (int nt = 0; nt < 8; nt++) {
                unsigned b0 = Bsp[(nt * 8 + g) * 68 + ks * 8 + tg];
                unsigned b1 = Bsp[(nt * 8 + g) * 68 + ks * 8 + tg + 4];
                mma_bf16(acc[nt], a0, a1, a2, a3, b0, b1);
            }
        }
    }
    __syncthreads();

    // stage M tile (f32, rows 64 x cols 64, pitch 68 floats) into same smem
    float* Ms = (float*)mms;
    #pragma unroll
    for (int nt = 0; nt < 8; nt++) {
        int col = nt * 8 + tg * 2;
        Ms[(w * 16 + g)     * 68 + col]     = acc[nt][0];
        Ms[(w * 16 + g)     * 68 + col + 1] = acc[nt][1];
        Ms[(w * 16 + g + 8) * 68 + col]     = acc[nt][2];
        Ms[(w * 16 + g + 8) * 68 + col + 1] = acc[nt][3];
    }
    __syncthreads();

    // epilogue: g_bp[u][j][c] = sum_s Wr[c][j][u][s] * M[uc][j*16+s]
    #pragma unroll
    for (int rep = 0; rep < 2; rep++) {
        int o = rep * 128 + t;               // 0..255
        int row = o >> 2, jl = o & 3;
        int uc = mb * 64 + row;
        int u = uc >> 11, c = uc & 2047;
        int j = nb * 4 + jl;
        const float4* wr = (const float4*)&g_Wr[(((size_t)c * JJ + j) * UU + u) * SS];
        const float* mrow = Ms + row * 68 + jl * 16;
        float dot = 0.0f;
        #pragma unroll
        for (int q = 0; q < 4; q++) {
            float4 wv = wr[q];
            dot = fmaf(wv.x, mrow[q*4+0],
                  fmaf(wv.y, mrow[q*4+1],
                  fmaf(wv.z, mrow[q*4+2],
                  fmaf(wv.w, mrow[q*4+3], dot))));
        }
        g_bp[((size_t)u * JJ + j) * CC + c] = dot;
    }
}

// ---------------- fused b-update reduce + softmax -------------------------------
__global__ void bsoftmax_k() {
    int j = blockIdx.x;
    int t = threadIdx.x;
    __shared__ float redm[16];
    __shared__ float reds[16];
    float4 bv = ((const float4*)(g_b + (size_t)j * CC))[t];
    float4 su = make_float4(0.f, 0.f, 0.f, 0.f);
    #pragma unroll
    for (int u = 0; u < UU; u++) {
        float4 p = ((const float4*)(g_bp + ((size_t)u * JJ + j) * CC))[t];
        su.x += p.x; su.y += p.y; su.z += p.z; su.w += p.w;
    }
    const float inv_b = 1.0f / (float)BB;
    bv.x += su.x * inv_b; bv.y += su.y * inv_b;
    bv.z += su.z * inv_b; bv.w += su.w * inv_b;
    ((float4*)(g_b + (size_t)j * CC))[t] = bv;

    float mx = fmaxf(fmaxf(bv.x, bv.y), fmaxf(bv.z, bv.w));
    #pragma unroll
    for (int o = 16; o > 0; o >>= 1) mx = fmaxf(mx, __shfl_xor_sync(0xffffffffu, mx, o));
    if ((t & 31) == 0) redm[t >> 5] = mx;
    __syncthreads();
    float bmax = redm[0];
    #pragma unroll
    for (int i = 1; i < 16; i++) bmax = fmaxf(bmax, redm[i]);
    float4 e;
    e.x = __expf(bv.x - bmax); e.y = __expf(bv.y - bmax);
    e.z = __expf(bv.z - bmax); e.w = __expf(bv.w - bmax);
    float sm = e.x + e.y + e.z + e.w;
    #pragma unroll
    for (int o = 16; o > 0; o >>= 1) sm += __shfl_xor_sync(0xffffffffu, sm, o);
    if ((t & 31) == 0) reds[t >> 5] = sm;
    __syncthreads();
    float tot = 0.0f;
    #pragma unroll
    for (int i = 0; i < 16; i++) tot += reds[i];
    float inv = 1.0f / tot;
    e.x *= inv; e.y *= inv; e.z *= inv; e.w *= inv;
    ((float4*)(g_c + (size_t)j * CC))[t] = e;
}

// ---------------- launcher --------------------------------------------------------
extern "C" void kernel_launch(void* const* d_in, const int* in_sizes, int n_in,
                              void* d_out, int out_size) {
    const float* x = (const float*)d_in[0];   // [B,U,C]
    const float* W = (const float*)d_in[1];   // [1,C,J,S,U]
    float* out = (float*)d_out;               // [B,J,S,1]

    setup_k<<<2048 + 32768 + 64, 256>>>(x, W);
    setup2_k<<<256, 256>>>();

    for (int it = 0; it < NITER; it++) {
        s_pass_k<<<dim3(JJ/2, NCHUNK), 256>>>();
        squash_k<<<BB, 512>>>(out, it < NITER - 1 ? 1 : 0);
        if (it < NITER - 1) {
            mgemm_mma_k<<<dim3(8, 256), 128, MM_SMEM>>>();
            bsoftmax_k<<<JJ, 512>>>();
        }
    }
}

// round 15
// speedup vs baseline: 1.5033x; 1.5033x over previous
#include <cuda_runtime.h>

#define BB 128
#define UU 8
#define CC 2048
#define JJ 32
#define SS 16
#define NITER 3

#define JS   (JJ*SS)     // 512
#define SU   (SS*UU)     // 128
#define JSU  (JJ*SS*UU)  // 4096
#define UC   (UU*CC)     // 16384
#define CB   (CC*BB)     // 262144
#define NCHUNK 64        // 64 chunks of 32 c

typedef unsigned long long ull;

// ---------------- packed f32x2 helpers ---------------------------------------
__device__ __forceinline__ ull pk2(float lo, float hi) {
    ull r; asm("mov.b64 %0, {%1, %2};" : "=l"(r) : "f"(lo), "f"(hi)); return r;
}
__device__ __forceinline__ void fma2(ull& d, ull a, ull b) {
    asm("fma.rn.f32x2 %0, %1, %2, %0;" : "+l"(d) : "l"(a), "l"(b));
}
__device__ __forceinline__ void add2(ull& d, ull a) {
    asm("add.rn.f32x2 %0, %0, %1;" : "+l"(d) : "l"(a));
}
__device__ __forceinline__ void upk2(float& lo, float& hi, ull v) {
    asm("mov.b64 {%0, %1}, %2;" : "=f"(lo), "=f"(hi) : "l"(v));
}
__device__ __forceinline__ void cpasync16(unsigned smem, const void* g) {
    asm volatile("cp.async.cg.shared.global [%0], [%1], 16;" :: "r"(smem), "l"(g));
}
#define CP_COMMIT() asm volatile("cp.async.commit_group;" ::: "memory")
#define CP_WAIT(n)  asm volatile("cp.async.wait_group %0;" :: "n"(n) : "memory")

// ---------------- device scratch ----------------------------------------------
__device__ float g_xT[UU*CC*BB + 256];   // [u][c][b]  8 MB (+pad for prefetch)
__device__ float g_Wr[CC*JSU];           // [c][j][u][s] 33.5 MB
__device__ float g_b[JJ*CC];             // logits [j][c]
__device__ float g_c[JJ*CC];             // coeffs [j][c]
__device__ float g_sp[NCHUNK*BB*JS];     // partial s, 16 MB
__device__ float g_bp[UU*JJ*CC];         // per-u partial b-updates [u][j][c], 2 MB

// ---------------- fused setup: transpose x, reorder W, init b/c ----------------
__global__ void __launch_bounds__(256) setup_k(const float* __restrict__ x,
                                               const float* __restrict__ Wg) {
    int bid = blockIdx.x;
    int t   = threadIdx.x;
    if (bid < 2048) {
        __shared__ float tile[32][33];
        int ct = bid & 63;
        int bt = (bid >> 6) & 3;
        int u  = bid >> 8;
        int c0 = ct * 32, b0 = bt * 32;
        int tx = t & 31, ty8 = t >> 5;
        #pragma unroll
        for (int r = 0; r < 4; r++) {
            int ty = ty8 + r * 8;
            tile[ty][tx] = x[(size_t)(b0 + ty) * UC + u * CC + c0 + tx];
        }
        __syncthreads();
        #pragma unroll
        for (int r = 0; r < 4; r++) {
            int ty = ty8 + r * 8;
            g_xT[(size_t)u * CB + (size_t)(c0 + ty) * BB + b0 + tx] = tile[tx][ty];
        }
    } else if (bid < 2048 + 32768) {
        int row = (bid - 2048) * 2 + (t >> 7);   // c*J + j
        int tt  = t & 127;                       // u*16+s
        int u = tt >> 4, s = tt & 15;
        g_Wr[(size_t)row * SU + tt] = Wg[(size_t)row * SU + s * UU + u];
    } else {
        int i = (bid - 2048 - 32768) * 256 + t;  // 0..16383 float4
        ((float4*)g_b)[i] = make_float4(0.f, 0.f, 0.f, 0.f);
        float cv = 1.0f / 2048.0f;
        ((float4*)g_c)[i] = make_float4(cv, cv, cv, cv);
    }
}

// ---------------- fused s-pass (warp = 1 j, 8 c, all 128 b, 16 s) ----------------
// s[b,j,s] = sum_c coef[j,c] * sum_u Wr[c,j,u,s] * xT[u,c,b]
// block = (j-pair, chunk of 32 c), 256 threads = 8 warps.
// warp w: jj = w&1 (j), cq = w>>1 (c-quarter, 8 c). Lane owns b = lane*4..+3
// (LDG.128, depth-2 prefetch).
__global__ void __launch_bounds__(256, 2) s_pass_k() {
    int j0    = blockIdx.x * 2;   // 16 j-pairs
    int chunk = blockIdx.y;       // 64
    int t     = threadIdx.x;
    int w = t >> 5, lane = t & 31;
    int jj = w & 1, cq = w >> 1;  // cq 0..3
    int cbase = chunk * 32;

    __shared__ __align__(16) float wsm[2 * 32 * 128];  // 32 KB (stage, then reduce)

    // stage coef-scaled W for both j's: 2048 float4 = 8 per thread
    {
        const float4* Wr4 = (const float4*)g_Wr;
        float4* w4 = (float4*)wsm;
        #pragma unroll
        for (int i = 0; i < 8; i++) {
            int lin = i * 256 + t;          // 0..2047
            int sj = lin >> 10;
            int rem = lin & 1023;
            int cl = rem >> 5, q = rem & 31;
            float coef = __ldg(&g_c[(j0 + sj) * CC + cbase + cl]);
            float4 wv = Wr4[(size_t)(cbase + cl) * (JSU/4) + (j0 + sj) * 32 + q];
            wv.x *= coef; wv.y *= coef; wv.z *= coef; wv.w *= coef;
            w4[sj * 1024 + cl * 32 + q] = wv;
        }
    }
    __syncthreads();

    ull acc[4][8];   // [bi][sp]
    #pragma unroll
    for (int bi = 0; bi < 4; bi++)
        #pragma unroll
        for (int sp = 0; sp < 8; sp++) acc[bi][sp] = 0ULL;

    const float* xrow0 = g_xT + (size_t)(cbase + cq * 8) * BB + lane * 4;  // (k,u)=(0,0)
    const float* wwarp = &wsm[jj * 4096 + cq * 8 * 128];

    // depth-2 prefetch pipeline over flattened (k,u)
    float4 x0 = *(const float4*)(xrow0);            // (0,0)
    float4 x1 = *(const float4*)(xrow0 + CB);       // (0,1)

    #pragma unroll 1
    for (int k = 0; k < 8; k++) {
        const float* xrow = xrow0 + k * BB;
        #pragma unroll
        for (int u = 0; u < UU; u++) {
            // prefetch (k,u)+2 : offset ((u+2)&7)*CB + ((u+2)>>3)*BB  (compile-time)
            float4 x2 = *(const float4*)(xrow + ((u + 2) & 7) * CB + ((u + 2) >> 3) * BB);

            ull xd0 = pk2(x0.x, x0.x), xd1 = pk2(x0.y, x0.y);
            ull xd2 = pk2(x0.z, x0.z), xd3 = pk2(x0.w, x0.w);
            const ulonglong2* w2 = (const ulonglong2*)(wwarp + k * 128 + u * 16);
            ulonglong2 wv0 = w2[0], wv1 = w2[1], wv2 = w2[2], wv3 = w2[3];
            ull wp[8] = {wv0.x, wv0.y, wv1.x, wv1.y, wv2.x, wv2.y, wv3.x, wv3.y};
            #pragma unroll
            for (int sp = 0; sp < 8; sp++) {
                fma2(acc[0][sp], wp[sp], xd0);
                fma2(acc[1][sp], wp[sp], xd1);
                fma2(acc[2][sp], wp[sp], xd2);
                fma2(acc[3][sp], wp[sp], xd3);
            }
            x0 = x1; x1 = x2;
        }
    }

    // reduce over 4 c-quarters: cq{2,3} store regions {0,1}; cq{0,1} add into them;
    // then all threads sum region0+region1. slot = bi*32 + lane (conflict-free).
    __syncthreads();
    ull* redU = (ull*)wsm;   // 4096 ULL = 32 KB
    if (cq >= 2) {
        #pragma unroll
        for (int bi = 0; bi < 4; bi++)
            #pragma unroll
            for (int sp = 0; sp < 8; sp++)
                redU[jj*2048 + (cq-2)*1024 + sp*128 + bi*32 + lane] = acc[bi][sp];
    }
    __syncthreads();
    if (cq < 2) {
        #pragma unroll
        for (int bi = 0; bi < 4; bi++)
            #pragma unroll
            for (int sp = 0; sp < 8; sp++) {
                int idx = jj*2048 + cq*1024 + sp*128 + bi*32 + lane;
                ull s = redU[idx];
                add2(s, acc[bi][sp]);
                redU[idx] = s;
            }
    }
    __syncthreads();

    // all 256 threads: jj = t>>7, slot = t&127 -> b = (slot&31)*4 + (slot>>5)
    {
        int sj = t >> 7, slot = t & 127;
        int b = (slot & 31) * 4 + (slot >> 5);
        float res[16];
        #pragma unroll
        for (int sp = 0; sp < 8; sp++) {
            ull s = redU[sj*2048 + sp*128 + slot];
            add2(s, redU[sj*2048 + 1024 + sp*128 + slot]);
            upk2(res[2*sp], res[2*sp+1], s);
        }
        float4* dst = (float4*)&g_sp[(size_t)chunk * (BB*JS) + b * JS + (j0 + sj) * SS];
        #pragma unroll
        for (int q = 0; q < 4; q++)
            dst[q] = make_float4(res[q*4], res[q*4+1], res[q*4+2], res[q*4+3]);
    }
}

// ---------------- reduce partials + squash -> v (float4 per thread) -------------
__global__ void squash_k(float* __restrict__ out) {
    int b = blockIdx.x;      // 128
    int t = threadIdx.x;     // 128; thread owns js = t*4..t*4+3
    float4 sv = make_float4(0.f, 0.f, 0.f, 0.f);
    #pragma unroll 8
    for (int k = 0; k < NCHUNK; k++) {
        float4 p = *(const float4*)&g_sp[(size_t)k * (BB*JS) + b * JS + t * 4];
        sv.x += p.x; sv.y += p.y; sv.z += p.z; sv.w += p.w;
    }

    __shared__ float sq[512];
    __shared__ float msqs[SS];
    sq[t*4+0] = sv.x * sv.x;
    sq[t*4+1] = sv.y * sv.y;
    sq[t*4+2] = sv.z * sv.z;
    sq[t*4+3] = sv.w * sv.w;
    __syncthreads();
    if (t < SS) {
        float m = 0.0f;
        #pragma unroll
        for (int jj = 0; jj < JJ; jj++) m += sq[jj * SS + t];
        msqs[t] = m;
    }
    __syncthreads();
    // js = t*4+q ; s = (t*4+q) & 15
    float4 res;
    {
        float m0 = msqs[(t*4+0) & 15];
        float m1 = msqs[(t*4+1) & 15];
        float m2 = msqs[(t*4+2) & 15];
        float m3 = msqs[(t*4+3) & 15];
        res.x = sv.x * (m0 / ((1.0f + m0) * sqrtf(m0)));
        res.y = sv.y * (m1 / ((1.0f + m1) * sqrtf(m1)));
        res.z = sv.z * (m2 / ((1.0f + m2) * sqrtf(m2)));
        res.w = sv.w * (m3 / ((1.0f + m3) * sqrtf(m3)));
    }
    *(float4*)&out[b * JS + t * 4] = res;
}

// ---------------- fused M-GEMM + b-update epilogue ------------------------------
// M[(u,c),(j,s)] = sum_b x[b][(u,c)] * v[b][(j,s)]  — A is x itself (no transpose).
// 256x64 tile, 256 thr, thread = 8 rows (f32x2 row-pairs) x 8 cols.
// cp.async double-buffered staging. Epilogue dots with Wr -> g_bp[u][j][c].
#define MG_STAGE_F 10240   // floats per stage: As 32*256=8192 + Bs 32*64=2048
__global__ void __launch_bounds__(256, 2) mgemm_k(const float* __restrict__ x,
                                                  const float* __restrict__ v) {
    extern __shared__ __align__(16) float dsm[];
    int col0 = blockIdx.x * 64;    // 8
    int row0 = blockIdx.y * 256;   // 64  (one u: 256 | 2048)
    int t  = threadIdx.x;
    int tr = t >> 3;               // 0..31 -> rows tr*8..+8
    int tc = t & 7;                // 0..7  -> cols tc*8..+8

    unsigned smem_u32;
    { unsigned long long tmp = __cvta_generic_to_shared(dsm); smem_u32 = (unsigned)tmp; }

    ull acc[4][8];   // [row-pair][col]
    #pragma unroll
    for (int i = 0; i < 4; i++)
        #pragma unroll
        for (int q = 0; q < 8; q++) acc[i][q] = 0ULL;

    // issue stage 0
    {
        unsigned sb = smem_u32;
        #pragma unroll
        for (int i = 0; i < 8; i++) {
            int lin = i * 256 + t;            // A: 2048 float4
            int kk = lin >> 6, q = lin & 63;
            cpasync16(sb + kk * 1024 + q * 16, x + (size_t)kk * UC + row0 + q * 4);
        }
        #pragma unroll
        for (int i = 0; i < 2; i++) {
            int lin = i * 256 + t;            // B: 512 float4
            int kk = lin >> 4, q = lin & 15;
            cpasync16(sb + 32768 + kk * 256 + q * 16, v + (size_t)kk * JS + col0 + q * 4);
        }
        CP_COMMIT();
    }

    #pragma unroll 1
    for (int i = 0; i < 4; i++) {
        if (i < 3) {
            int k0n = (i + 1) * 32;
            unsigned sb = smem_u32 + ((i + 1) & 1) * (MG_STAGE_F * 4);
            #pragma unroll
            for (int q8 = 0; q8 < 8; q8++) {
                int lin = q8 * 256 + t;
                int kk = lin >> 6, q = lin & 63;
                cpasync16(sb + kk * 1024 + q * 16,
                          x + (size_t)(k0n + kk) * UC + row0 + q * 4);
            }
            #pragma unroll
            for (int q2 = 0; q2 < 2; q2++) {
                int lin = q2 * 256 + t;
                int kk = lin >> 4, q = lin & 15;
                cpasync16(sb + 32768 + kk * 256 + q * 16,
                          v + (size_t)(k0n + kk) * JS + col0 + q * 4);
            }
            CP_COMMIT();
            CP_WAIT(1);
        } else {
            CP_WAIT(0);
        }
        __syncthreads();

        const float* As = dsm + (i & 1) * MG_STAGE_F;
        const float* Bs = As + 32 * 256;
        #pragma unroll 8
        for (int kk = 0; kk < 32; kk++) {
            ulonglong2 ap0 = *(const ulonglong2*)&As[kk * 256 + tr * 8];
            ulonglong2 ap1 = *(const ulonglong2*)&As[kk * 256 + tr * 8 + 4];
            float4 b0 = *(const float4*)&Bs[kk * 64 + tc * 8];
            float4 b1 = *(const float4*)&Bs[kk * 64 + tc * 8 + 4];
            ull bd[8];
            bd[0] = pk2(b0.x, b0.x); bd[1] = pk2(b0.y, b0.y);
            bd[2] = pk2(b0.z, b0.z); bd[3] = pk2(b0.w, b0.w);
            bd[4] = pk2(b1.x, b1.x); bd[5] = pk2(b1.y, b1.y);
            bd[6] = pk2(b1.z, b1.z); bd[7] = pk2(b1.w, b1.w);
            ull ap[4] = {ap0.x, ap0.y, ap1.x, ap1.y};
            #pragma unroll
            for (int rp = 0; rp < 4; rp++)
                #pragma unroll
                for (int q = 0; q < 8; q++)
                    fma2(acc[rp][q], ap[rp], bd[q]);
        }
        __syncthreads();
    }

    // epilogue: thread cols = (one j, 8 s at s0); rows tr*8..+8 (pairs).
    int u  = row0 >> 11;
    int j  = (col0 >> 4) + (tc >> 1);
    int s0 = (tc & 1) * 8;
    #pragma unroll
    for (int rp = 0; rp < 4; rp++) {
        int clo = (row0 & 2047) + tr * 8 + rp * 2;
        float mlo[8], mhi[8];
        #pragma unroll
        for (int q = 0; q < 8; q++) upk2(mlo[q], mhi[q], acc[rp][q]);
        const float4* wlo = (const float4*)&g_Wr[(((size_t)clo * JJ + j) * UU + u) * SS + s0];
        const float4* whi = (const float4*)&g_Wr[(((size_t)(clo+1) * JJ + j) * UU + u) * SS + s0];
        float4 wl0 = wlo[0], wl1 = wlo[1];
        float4 wh0 = whi[0], wh1 = whi[1];
        float dlo = wl0.x*mlo[0] + wl0.y*mlo[1] + wl0.z*mlo[2] + wl0.w*mlo[3]
                  + wl1.x*mlo[4] + wl1.y*mlo[5] + wl1.z*mlo[6] + wl1.w*mlo[7];
        float dhi = wh0.x*mhi[0] + wh0.y*mhi[1] + wh0.z*mhi[2] + wh0.w*mhi[3]
                  + wh1.x*mhi[4] + wh1.y*mhi[5] + wh1.z*mhi[6] + wh1.w*mhi[7];
        float olo = __shfl_xor_sync(0xffffffffu, dlo, 1);
        float ohi = __shfl_xor_sync(0xffffffffu, dhi, 1);
        if ((tc & 1) == 0) {
            g_bp[((size_t)u * JJ + j) * CC + clo]     = dlo + olo;
            g_bp[((size_t)u * JJ + j) * CC + clo + 1] = dhi + ohi;
        }
    }
}

// ---------------- fused b-update reduce + softmax -------------------------------
__global__ void bsoftmax_k() {
    int j = blockIdx.x;       // 32
    int t = threadIdx.x;      // 512
    __shared__ float redm[16];
    __shared__ float reds[16];
    float4 bv = ((const float4*)(g_b + (size_t)j * CC))[t];
    float4 su = make_float4(0.f, 0.f, 0.f, 0.f);
    #pragma unroll
    for (int u = 0; u < UU; u++) {
        float4 p = ((const float4*)(g_bp + ((size_t)u * JJ + j) * CC))[t];
        su.x += p.x; su.y += p.y; su.z += p.z; su.w += p.w;
    }
    const float inv_b = 1.0f / (float)BB;
    bv.x += su.x * inv_b; bv.y += su.y * inv_b;
    bv.z += su.z * inv_b; bv.w += su.w * inv_b;
    ((float4*)(g_b + (size_t)j * CC))[t] = bv;

    float mx = fmaxf(fmaxf(bv.x, bv.y), fmaxf(bv.z, bv.w));
    #pragma unroll
    for (int o = 16; o > 0; o >>= 1) mx = fmaxf(mx, __shfl_xor_sync(0xffffffffu, mx, o));
    if ((t & 31) == 0) redm[t >> 5] = mx;
    __syncthreads();
    float bmax = redm[0];
    #pragma unroll
    for (int i = 1; i < 16; i++) bmax = fmaxf(bmax, redm[i]);
    float4 e;
    e.x = __expf(bv.x - bmax); e.y = __expf(bv.y - bmax);
    e.z = __expf(bv.z - bmax); e.w = __expf(bv.w - bmax);
    float sm = e.x + e.y + e.z + e.w;
    #pragma unroll
    for (int o = 16; o > 0; o >>= 1) sm += __shfl_xor_sync(0xffffffffu, sm, o);
    if ((t & 31) == 0) reds[t >> 5] = sm;
    __syncthreads();
    float tot = 0.0f;
    #pragma unroll
    for (int i = 0; i < 16; i++) tot += reds[i];
    float inv = 1.0f / tot;
    e.x *= inv; e.y *= inv; e.z *= inv; e.w *= inv;
    ((float4*)(g_c + (size_t)j * CC))[t] = e;
}

// ---------------- launcher --------------------------------------------------------
extern "C" void kernel_launch(void* const* d_in, const int* in_sizes, int n_in,
                              void* d_out, int out_size) {
    const float* x = (const float*)d_in[0];   // [B,U,C]
    const float* W = (const float*)d_in[1];   // [1,C,J,S,U]
    float* out = (float*)d_out;               // [B,J,S,1]

    cudaFuncSetAttribute(mgemm_k, cudaFuncAttributeMaxDynamicSharedMemorySize,
                         2 * MG_STAGE_F * 4);

    setup_k<<<2048 + 32768 + 64, 256>>>(x, W);

    for (int it = 0; it < NITER; it++) {
        s_pass_k<<<dim3(JJ/2, NCHUNK), 256>>>();
        squash_k<<<BB, 128>>>(out);
        if (it < NITER - 1) {
            mgemm_k<<<dim3(JS/64, UC/256), 256, 2 * MG_STAGE_F * 4>>>(x, out);
            bsoftmax_k<<<JJ, 512>>>();
        }
    }
}

// round 16
// speedup vs baseline: 1.5553x; 1.0346x over previous
#include <cuda_runtime.h>

#define BB 128
#define UU 8
#define CC 2048
#define JJ 32
#define SS 16
#define NITER 3

#define JS   (JJ*SS)     // 512
#define SU   (SS*UU)     // 128
#define JSU  (JJ*SS*UU)  // 4096
#define UC   (UU*CC)     // 16384
#define CB   (CC*BB)     // 262144
#define NCHUNK 64        // 64 chunks of 32 c

typedef unsigned long long ull;

// ---------------- packed f32x2 helpers ---------------------------------------
__device__ __forceinline__ ull pk2(float lo, float hi) {
    ull r; asm("mov.b64 %0, {%1, %2};" : "=l"(r) : "f"(lo), "f"(hi)); return r;
}
__device__ __forceinline__ void fma2(ull& d, ull a, ull b) {
    asm("fma.rn.f32x2 %0, %1, %2, %0;" : "+l"(d) : "l"(a), "l"(b));
}
__device__ __forceinline__ void add2(ull& d, ull a) {
    asm("add.rn.f32x2 %0, %0, %1;" : "+l"(d) : "l"(a));
}
__device__ __forceinline__ void upk2(float& lo, float& hi, ull v) {
    asm("mov.b64 {%0, %1}, %2;" : "=f"(lo), "=f"(hi) : "l"(v));
}
__device__ __forceinline__ void cpasync16(unsigned smem, const void* g) {
    asm volatile("cp.async.cg.shared.global [%0], [%1], 16;" :: "r"(smem), "l"(g));
}
#define CP_COMMIT() asm volatile("cp.async.commit_group;" ::: "memory")
#define CP_WAIT(n)  asm volatile("cp.async.wait_group %0;" :: "n"(n) : "memory")

// ---------------- device scratch ----------------------------------------------
__device__ float g_xT[UU*CC*BB + 256];   // [u][c][b]  8 MB (+pad for prefetch)
__device__ float g_Wr[CC*JSU];           // [c][j][u][s] 33.5 MB
__device__ float g_b[JJ*CC];             // logits [j][c]
__device__ float g_c[JJ*CC];             // coeffs [j][c]
__device__ float g_sp[NCHUNK*BB*JS];     // partial s, 16 MB
__device__ float g_bp[UU*JJ*CC];         // per-u partial b-updates [u][j][c], 2 MB

// ---------------- fused setup: transpose x, reorder W, init b/c ----------------
__global__ void __launch_bounds__(256) setup_k(const float* __restrict__ x,
                                               const float* __restrict__ Wg) {
    int bid = blockIdx.x;
    int t   = threadIdx.x;
    if (bid < 2048) {
        __shared__ float tile[32][33];
        int ct = bid & 63;
        int bt = (bid >> 6) & 3;
        int u  = bid >> 8;
        int c0 = ct * 32, b0 = bt * 32;
        int tx = t & 31, ty8 = t >> 5;
        #pragma unroll
        for (int r = 0; r < 4; r++) {
            int ty = ty8 + r * 8;
            tile[ty][tx] = x[(size_t)(b0 + ty) * UC + u * CC + c0 + tx];
        }
        __syncthreads();
        #pragma unroll
        for (int r = 0; r < 4; r++) {
            int ty = ty8 + r * 8;
            g_xT[(size_t)u * CB + (size_t)(c0 + ty) * BB + b0 + tx] = tile[tx][ty];
        }
    } else if (bid < 2048 + 32768) {
        int row = (bid - 2048) * 2 + (t >> 7);   // c*J + j
        int tt  = t & 127;                       // u*16+s
        int u = tt >> 4, s = tt & 15;
        g_Wr[(size_t)row * SU + tt] = Wg[(size_t)row * SU + s * UU + u];
    } else {
        int i = (bid - 2048 - 32768) * 256 + t;  // 0..16383 float4
        ((float4*)g_b)[i] = make_float4(0.f, 0.f, 0.f, 0.f);
        float cv = 1.0f / 2048.0f;
        ((float4*)g_c)[i] = make_float4(cv, cv, cv, cv);
    }
}

// ---------------- fused s-pass (warp = 1 j, 8 c, all 128 b, 16 s) ----------------
// s[b,j,s] = sum_c coef[j,c] * sum_u Wr[c,j,u,s] * xT[u,c,b]
// block = (j-pair, chunk of 32 c), 256 threads = 8 warps.
// warp w: jj = w&1 (j), cq = w>>1 (c-quarter, 8 c). Lane owns b = lane*4..+3
// (LDG.128, depth-2 prefetch).
__global__ void __launch_bounds__(256, 2) s_pass_k() {
    int j0    = blockIdx.x * 2;   // 16 j-pairs
    int chunk = blockIdx.y;       // 64
    int t     = threadIdx.x;
    int w = t >> 5, lane = t & 31;
    int jj = w & 1, cq = w >> 1;  // cq 0..3
    int cbase = chunk * 32;

    __shared__ __align__(16) float wsm[2 * 32 * 128];  // 32 KB (stage, then reduce)

    // stage coef-scaled W for both j's: 2048 float4 = 8 per thread
    {
        const float4* Wr4 = (const float4*)g_Wr;
        float4* w4 = (float4*)wsm;
        #pragma unroll
        for (int i = 0; i < 8; i++) {
            int lin = i * 256 + t;          // 0..2047
            int sj = lin >> 10;
            int rem = lin & 1023;
            int cl = rem >> 5, q = rem & 31;
            float coef = __ldg(&g_c[(j0 + sj) * CC + cbase + cl]);
            float4 wv = Wr4[(size_t)(cbase + cl) * (JSU/4) + (j0 + sj) * 32 + q];
            wv.x *= coef; wv.y *= coef; wv.z *= coef; wv.w *= coef;
            w4[sj * 1024 + cl * 32 + q] = wv;
        }
    }
    __syncthreads();

    ull acc[4][8];   // [bi][sp]
    #pragma unroll
    for (int bi = 0; bi < 4; bi++)
        #pragma unroll
        for (int sp = 0; sp < 8; sp++) acc[bi][sp] = 0ULL;

    const float* xrow0 = g_xT + (size_t)(cbase + cq * 8) * BB + lane * 4;  // (k,u)=(0,0)
    const float* wwarp = &wsm[jj * 4096 + cq * 8 * 128];

    // depth-2 prefetch pipeline over flattened (k,u)
    float4 x0 = *(const float4*)(xrow0);            // (0,0)
    float4 x1 = *(const float4*)(xrow0 + CB);       // (0,1)

    #pragma unroll 1
    for (int k = 0; k < 8; k++) {
        const float* xrow = xrow0 + k * BB;
        #pragma unroll
        for (int u = 0; u < UU; u++) {
            // prefetch (k,u)+2 : offset ((u+2)&7)*CB + ((u+2)>>3)*BB  (compile-time)
            float4 x2 = *(const float4*)(xrow + ((u + 2) & 7) * CB + ((u + 2) >> 3) * BB);

            ull xd0 = pk2(x0.x, x0.x), xd1 = pk2(x0.y, x0.y);
            ull xd2 = pk2(x0.z, x0.z), xd3 = pk2(x0.w, x0.w);
            const ulonglong2* w2 = (const ulonglong2*)(wwarp + k * 128 + u * 16);
            ulonglong2 wv0 = w2[0], wv1 = w2[1], wv2 = w2[2], wv3 = w2[3];
            ull wp[8] = {wv0.x, wv0.y, wv1.x, wv1.y, wv2.x, wv2.y, wv3.x, wv3.y};
            #pragma unroll
            for (int sp = 0; sp < 8; sp++) {
                fma2(acc[0][sp], wp[sp], xd0);
                fma2(acc[1][sp], wp[sp], xd1);
                fma2(acc[2][sp], wp[sp], xd2);
                fma2(acc[3][sp], wp[sp], xd3);
            }
            x0 = x1; x1 = x2;
        }
    }

    // reduce over 4 c-quarters: cq{2,3} store regions {0,1}; cq{0,1} add into them;
    // then all threads sum region0+region1. slot = bi*32 + lane (conflict-free).
    __syncthreads();
    ull* redU = (ull*)wsm;   // 4096 ULL = 32 KB
    if (cq >= 2) {
        #pragma unroll
        for (int bi = 0; bi < 4; bi++)
            #pragma unroll
            for (int sp = 0; sp < 8; sp++)
                redU[jj*2048 + (cq-2)*1024 + sp*128 + bi*32 + lane] = acc[bi][sp];
    }
    __syncthreads();
    if (cq < 2) {
        #pragma unroll
        for (int bi = 0; bi < 4; bi++)
            #pragma unroll
            for (int sp = 0; sp < 8; sp++) {
                int idx = jj*2048 + cq*1024 + sp*128 + bi*32 + lane;
                ull s = redU[idx];
                add2(s, acc[bi][sp]);
                redU[idx] = s;
            }
    }
    __syncthreads();

    // all 256 threads: jj = t>>7, slot = t&127 -> b = (slot&31)*4 + (slot>>5)
    {
        int sj = t >> 7, slot = t & 127;
        int b = (slot & 31) * 4 + (slot >> 5);
        float res[16];
        #pragma unroll
        for (int sp = 0; sp < 8; sp++) {
            ull s = redU[sj*2048 + sp*128 + slot];
            add2(s, redU[sj*2048 + 1024 + sp*128 + slot]);
            upk2(res[2*sp], res[2*sp+1], s);
        }
        float4* dst = (float4*)&g_sp[(size_t)chunk * (BB*JS) + b * JS + (j0 + sj) * SS];
        #pragma unroll
        for (int q = 0; q < 4; q++)
            dst[q] = make_float4(res[q*4], res[q*4+1], res[q*4+2], res[q*4+3]);
    }
}

// ---------------- reduce partials + squash -> v ---------------------------------
// 512 thr = 4 chunk-quarters x 128 float4-owners; quarter partials via smem.
__global__ void squash_k(float* __restrict__ out) {
    int b = blockIdx.x;      // 128
    int t = threadIdx.x;     // 512
    int q = t >> 7, tt = t & 127;

    float4 sv = make_float4(0.f, 0.f, 0.f, 0.f);
    #pragma unroll
    for (int k = q * 16; k < q * 16 + 16; k++) {
        float4 p = *(const float4*)&g_sp[(size_t)k * (BB*JS) + b * JS + tt * 4];
        sv.x += p.x; sv.y += p.y; sv.z += p.z; sv.w += p.w;
    }
    __shared__ __align__(16) float4 part[4][128];   // 8 KB
    __shared__ float sq[512];
    __shared__ float msqs[SS];
    part[q][tt] = sv;
    __syncthreads();

    float4 s4;
    if (t < 128) {
        float4 p0 = part[0][t], p1 = part[1][t], p2 = part[2][t], p3 = part[3][t];
        s4.x = p0.x + p1.x + p2.x + p3.x;
        s4.y = p0.y + p1.y + p2.y + p3.y;
        s4.z = p0.z + p1.z + p2.z + p3.z;
        s4.w = p0.w + p1.w + p2.w + p3.w;
        sq[t*4+0] = s4.x * s4.x;
        sq[t*4+1] = s4.y * s4.y;
        sq[t*4+2] = s4.z * s4.z;
        sq[t*4+3] = s4.w * s4.w;
    }
    __syncthreads();
    if (t < SS) {
        float m = 0.0f;
        #pragma unroll
        for (int jj = 0; jj < JJ; jj++) m += sq[jj * SS + t];
        msqs[t] = m;
    }
    __syncthreads();
    if (t < 128) {
        float m0 = msqs[(t*4+0) & 15];
        float m1 = msqs[(t*4+1) & 15];
        float m2 = msqs[(t*4+2) & 15];
        float m3 = msqs[(t*4+3) & 15];
        float4 res;
        res.x = s4.x * (m0 / ((1.0f + m0) * sqrtf(m0)));
        res.y = s4.y * (m1 / ((1.0f + m1) * sqrtf(m1)));
        res.z = s4.z * (m2 / ((1.0f + m2) * sqrtf(m2)));
        res.w = s4.w * (m3 / ((1.0f + m3) * sqrtf(m3)));
        *(float4*)&out[b * JS + t * 4] = res;
    }
}

// ---------------- fused M-GEMM + b-update epilogue ------------------------------
// M[(u,c),(j,s)] = sum_b x[b][(u,c)] * v[b][(j,s)]  — A is x itself (no transpose).
// 256x64 tile, 256 thr, thread = 8 rows (f32x2 row-pairs) x 8 cols.
// cp.async double-buffered staging. Epilogue dots with Wr -> g_bp[u][j][c].
#define MG_STAGE_F 10240   // floats per stage: As 32*256=8192 + Bs 32*64=2048
__global__ void __launch_bounds__(256, 2) mgemm_k(const float* __restrict__ x,
                                                  const float* __restrict__ v) {
    extern __shared__ __align__(16) float dsm[];
    int col0 = blockIdx.x * 64;    // 8
    int row0 = blockIdx.y * 256;   // 64  (one u: 256 | 2048)
    int t  = threadIdx.x;
    int tr = t >> 3;               // 0..31 -> rows tr*8..+8
    int tc = t & 7;                // 0..7  -> cols tc*8..+8

    unsigned smem_u32;
    { unsigned long long tmp = __cvta_generic_to_shared(dsm); smem_u32 = (unsigned)tmp; }

    ull acc[4][8];   // [row-pair][col]
    #pragma unroll
    for (int i = 0; i < 4; i++)
        #pragma unroll
        for (int q = 0; q < 8; q++) acc[i][q] = 0ULL;

    // issue stage 0
    {
        unsigned sb = smem_u32;
        #pragma unroll
        for (int i = 0; i < 8; i++) {
            int lin = i * 256 + t;            // A: 2048 float4
            int kk = lin >> 6, q = lin & 63;
            cpasync16(sb + kk * 1024 + q * 16, x + (size_t)kk * UC + row0 + q * 4);
        }
        #pragma unroll
        for (int i = 0; i < 2; i++) {
            int lin = i * 256 + t;            // B: 512 float4
            int kk = lin >> 4, q = lin & 15;
            cpasync16(sb + 32768 + kk * 256 + q * 16, v + (size_t)kk * JS + col0 + q * 4);
        }
        CP_COMMIT();
    }

    #pragma unroll 1
    for (int i = 0; i < 4; i++) {
        if (i < 3) {
            int k0n = (i + 1) * 32;
            unsigned sb = smem_u32 + ((i + 1) & 1) * (MG_STAGE_F * 4);
            #pragma unroll
            for (int q8 = 0; q8 < 8; q8++) {
                int lin = q8 * 256 + t;
                int kk = lin >> 6, q = lin & 63;
                cpasync16(sb + kk * 1024 + q * 16,
                          x + (size_t)(k0n + kk) * UC + row0 + q * 4);
            }
            #pragma unroll
            for (int q2 = 0; q2 < 2; q2++) {
                int lin = q2 * 256 + t;
                int kk = lin >> 4, q = lin & 15;
                cpasync16(sb + 32768 + kk * 256 + q * 16,
                          v + (size_t)(k0n + kk) * JS + col0 + q * 4);
            }
            CP_COMMIT();
            CP_WAIT(1);
        } else {
            CP_WAIT(0);
        }
        __syncthreads();

        const float* As = dsm + (i & 1) * MG_STAGE_F;
        const float* Bs = As + 32 * 256;
        #pragma unroll 8
        for (int kk = 0; kk < 32; kk++) {
            ulonglong2 ap0 = *(const ulonglong2*)&As[kk * 256 + tr * 8];
            ulonglong2 ap1 = *(const ulonglong2*)&As[kk * 256 + tr * 8 + 4];
            float4 b0 = *(const float4*)&Bs[kk * 64 + tc * 8];
            float4 b1 = *(const float4*)&Bs[kk * 64 + tc * 8 + 4];
            ull bd[8];
            bd[0] = pk2(b0.x, b0.x); bd[1] = pk2(b0.y, b0.y);
            bd[2] = pk2(b0.z, b0.z); bd[3] = pk2(b0.w, b0.w);
            bd[4] = pk2(b1.x, b1.x); bd[5] = pk2(b1.y, b1.y);
            bd[6] = pk2(b1.z, b1.z); bd[7] = pk2(b1.w, b1.w);
            ull ap[4] = {ap0.x, ap0.y, ap1.x, ap1.y};
            #pragma unroll
            for (int rp = 0; rp < 4; rp++)
                #pragma unroll
                for (int q = 0; q < 8; q++)
                    fma2(acc[rp][q], ap[rp], bd[q]);
        }
        __syncthreads();
    }

    // epilogue: thread cols = (one j, 8 s at s0); rows tr*8..+8 (pairs).
    int u  = row0 >> 11;
    int j  = (col0 >> 4) + (tc >> 1);
    int s0 = (tc & 1) * 8;
    #pragma unroll
    for (int rp = 0; rp < 4; rp++) {
        int clo = (row0 & 2047) + tr * 8 + rp * 2;
        float mlo[8], mhi[8];
        #pragma unroll
        for (int q = 0; q < 8; q++) upk2(mlo[q], mhi[q], acc[rp][q]);
        const float4* wlo = (const float4*)&g_Wr[(((size_t)clo * JJ + j) * UU + u) * SS + s0];
        const float4* whi = (const float4*)&g_Wr[(((size_t)(clo+1) * JJ + j) * UU + u) * SS + s0];
        float4 wl0 = wlo[0], wl1 = wlo[1];
        float4 wh0 = whi[0], wh1 = whi[1];
        float dlo = wl0.x*mlo[0] + wl0.y*mlo[1] + wl0.z*mlo[2] + wl0.w*mlo[3]
                  + wl1.x*mlo[4] + wl1.y*mlo[5] + wl1.z*mlo[6] + wl1.w*mlo[7];
        float dhi = wh0.x*mhi[0] + wh0.y*mhi[1] + wh0.z*mhi[2] + wh0.w*mhi[3]
                  + wh1.x*mhi[4] + wh1.y*mhi[5] + wh1.z*mhi[6] + wh1.w*mhi[7];
        float olo = __shfl_xor_sync(0xffffffffu, dlo, 1);
        float ohi = __shfl_xor_sync(0xffffffffu, dhi, 1);
        if ((tc & 1) == 0) {
            g_bp[((size_t)u * JJ + j) * CC + clo]     = dlo + olo;
            g_bp[((size_t)u * JJ + j) * CC + clo + 1] = dhi + ohi;
        }
    }
}

// ---------------- fused b-update reduce + softmax -------------------------------
__global__ void bsoftmax_k() {
    int j = blockIdx.x;       // 32
    int t = threadIdx.x;      // 512
    __shared__ float redm[16];
    __shared__ float reds[16];
    float4 bv = ((const float4*)(g_b + (size_t)j * CC))[t];
    float4 su = make_float4(0.f, 0.f, 0.f, 0.f);
    #pragma unroll
    for (int u = 0; u < UU; u++) {
        float4 p = ((const float4*)(g_bp + ((size_t)u * JJ + j) * CC))[t];
        su.x += p.x; su.y += p.y; su.z += p.z; su.w += p.w;
    }
    const float inv_b = 1.0f / (float)BB;
    bv.x += su.x * inv_b; bv.y += su.y * inv_b;
    bv.z += su.z * inv_b; bv.w += su.w * inv_b;
    ((float4*)(g_b + (size_t)j * CC))[t] = bv;

    float mx = fmaxf(fmaxf(bv.x, bv.y), fmaxf(bv.z, bv.w));
    #pragma unroll
    for (int o = 16; o > 0; o >>= 1) mx = fmaxf(mx, __shfl_xor_sync(0xffffffffu, mx, o));
    if ((t & 31) == 0) redm[t >> 5] = mx;
    __syncthreads();
    float bmax = redm[0];
    #pragma unroll
    for (int i = 1; i < 16; i++) bmax = fmaxf(bmax, redm[i]);
    float4 e;
    e.x = __expf(bv.x - bmax); e.y = __expf(bv.y - bmax);
    e.z = __expf(bv.z - bmax); e.w = __expf(bv.w - bmax);
    float sm = e.x + e.y + e.z + e.w;
    #pragma unroll
    for (int o = 16; o > 0; o >>= 1) sm += __shfl_xor_sync(0xffffffffu, sm, o);
    if ((t & 31) == 0) reds[t >> 5] = sm;
    __syncthreads();
    float tot = 0.0f;
    #pragma unroll
    for (int i = 0; i < 16; i++) tot += reds[i];
    float inv = 1.0f / tot;
    e.x *= inv; e.y *= inv; e.z *= inv; e.w *= inv;
    ((float4*)(g_c + (size_t)j * CC))[t] = e;
}

// ---------------- launcher --------------------------------------------------------
extern "C" void kernel_launch(void* const* d_in, const int* in_sizes, int n_in,
                              void* d_out, int out_size) {
    const float* x = (const float*)d_in[0];   // [B,U,C]
    const float* W = (const float*)d_in[1];   // [1,C,J,S,U]
    float* out = (float*)d_out;               // [B,J,S,1]

    cudaFuncSetAttribute(mgemm_k, cudaFuncAttributeMaxDynamicSharedMemorySize,
                         2 * MG_STAGE_F * 4);

    setup_k<<<2048 + 32768 + 64, 256>>>(x, W);

    for (int it = 0; it < NITER; it++) {
        s_pass_k<<<dim3(JJ/2, NCHUNK), 256>>>();
        squash_k<<<BB, 512>>>(out);
        if (it < NITER - 1) {
            mgemm_k<<<dim3(JS/64, UC/256), 256, 2 * MG_STAGE_F * 4>>>(x, out);
            bsoftmax_k<<<JJ, 512>>>();
        }
    }
}